// round 14
// baseline (speedup 1.0000x reference)
#include <cuda_runtime.h>
#include <cuda_fp16.h>
#include <cstdint>

// Problem constants
#define B_  2
#define T_  2048
#define D_  1024
#define H_  16
#define HD_ 64
#define M_ROWS (B_ * T_)   // 4096

// ---------------------------------------------------------------------------
// Scratch (allocation-free rule: __device__ globals)
// ---------------------------------------------------------------------------
__device__ __half g_xhi[(size_t)M_ROWS * D_];
__device__ __half g_xlo[(size_t)M_ROWS * D_];
__device__ __half g_wqkvhi[(size_t)3 * D_ * D_];
__device__ __half g_wqkvlo[(size_t)3 * D_ * D_];
__device__ __half g_wphi[(size_t)D_ * D_];
__device__ __half g_wplo[(size_t)D_ * D_];
__device__ __half g_qkvhi[(size_t)M_ROWS * 3 * D_];
__device__ __half g_qkvlo[(size_t)M_ROWS * 3 * D_];
__device__ __half g_yhi[(size_t)M_ROWS * D_];
__device__ __half g_ylo[(size_t)M_ROWS * D_];

// ---------------------------------------------------------------------------
// Helpers (baseline PTX only)
// ---------------------------------------------------------------------------
__device__ __forceinline__ uint32_t smem_u32(const void* p) {
    uint32_t a;
    asm("{ .reg .u64 t; cvta.to.shared.u64 t, %1; cvt.u32.u64 %0, t; }" : "=r"(a) : "l"(p));
    return a;
}

#define CP_ASYNC16(dst, src) \
    asm volatile("cp.async.cg.shared.global [%0], [%1], 16;" :: "r"(dst), "l"(src) : "memory")
#define CP_COMMIT() asm volatile("cp.async.commit_group;" ::: "memory")
#define CP_WAIT2()  asm volatile("cp.async.wait_group 2;" ::: "memory")
#define CP_WAIT1()  asm volatile("cp.async.wait_group 1;" ::: "memory")
#define CP_WAIT0()  asm volatile("cp.async.wait_group 0;" ::: "memory")

#define LDSM_X4(r0, r1, r2, r3, addr)                                          \
    asm volatile("ldmatrix.sync.aligned.m8n8.x4.shared.b16 {%0,%1,%2,%3}, [%4];" \
                 : "=r"(r0), "=r"(r1), "=r"(r2), "=r"(r3) : "r"(addr))

#define LDSM_X4_T(r0, r1, r2, r3, addr)                                        \
    asm volatile("ldmatrix.sync.aligned.m8n8.x4.trans.shared.b16 {%0,%1,%2,%3}, [%4];" \
                 : "=r"(r0), "=r"(r1), "=r"(r2), "=r"(r3) : "r"(addr))

#define MMA16816(c, a0, a1, a2, a3, b0, b1)                                    \
    asm volatile("mma.sync.aligned.m16n8k16.row.col.f32.f16.f16.f32 "          \
                 "{%0,%1,%2,%3}, {%4,%5,%6,%7}, {%8,%9}, {%0,%1,%2,%3};"       \
                 : "+f"((c)[0]), "+f"((c)[1]), "+f"((c)[2]), "+f"((c)[3])      \
                 : "r"(a0), "r"(a1), "r"(a2), "r"(a3), "r"(b0), "r"(b1))

__device__ __forceinline__ uint32_t f2h2(float a, float b) {
    __half2 t = __floats2half2_rn(a, b);
    return *reinterpret_cast<uint32_t*>(&t);
}
__device__ __forceinline__ uint32_t f2h2_lo(float a, float b, uint32_t hi) {
    __half2 h = *reinterpret_cast<__half2*>(&hi);
    __half2 t = __floats2half2_rn(a - __low2float(h), b - __high2float(h));
    return *reinterpret_cast<uint32_t*>(&t);
}
// 64B-row swizzle: 8 consecutive rows hit 8 distinct 16B banks per chunk.
__device__ __forceinline__ uint32_t swz64(uint32_t off) {
    return off ^ (((off >> 7) & 3) << 4);
}

// ---------------------------------------------------------------------------
// Split kernel: fp32 -> (hi, lo) fp16
// ---------------------------------------------------------------------------
__global__ void split_kernel(const float* __restrict__ in, __half* __restrict__ hi,
                             __half* __restrict__ lo, int n4) {
    int i = blockIdx.x * blockDim.x + threadIdx.x;
    if (i >= n4) return;
    float4 v = ((const float4*)in)[i];
    float f[4] = {v.x, v.y, v.z, v.w};
    __half h[4], l[4];
#pragma unroll
    for (int j = 0; j < 4; j++) {
        h[j] = __float2half_rn(f[j]);
        l[j] = __float2half_rn(f[j] - __half2float(h[j]));
    }
    ((__half2*)hi)[i * 2 + 0] = __halves2half2(h[0], h[1]);
    ((__half2*)hi)[i * 2 + 1] = __halves2half2(h[2], h[3]);
    ((__half2*)lo)[i * 2 + 0] = __halves2half2(l[0], l[1]);
    ((__half2*)lo)[i * 2 + 1] = __halves2half2(l[2], l[3]);
}

// ---------------------------------------------------------------------------
// HMMA fp16-split GEMM (3 passes), 3-stage cp.async pipeline, 1 sync/iter.
// CTA 128x128, 8 warps (2M x 4N), warp 64x32: acc=64 regs -> spill-free,
// 12 LDSM : 48 MMA per k16 (1:8 issue ratio, MMA-bound). 2 CTAs/SM.
// Mainloop ordering identical to the measured-best R8/R10 schedule.
// ---------------------------------------------------------------------------
#define GK_ARB  8192               // bytes per array (128 rows x 64 B)
#define GK_STGB 32768              // bytes per stage (Ahi,Alo,Bhi,Blo)
#define GK_SMEM (3 * GK_STGB)      // 98304 B

template <int N_, int K_, int OUT_SPLIT>
__global__ __launch_bounds__(256, 2) void hmma_gemm(
    const __half* __restrict__ Ahi, const __half* __restrict__ Alo,
    const __half* __restrict__ Bhi, const __half* __restrict__ Blo,
    float* __restrict__ C, __half* __restrict__ Chi, __half* __restrict__ Clo)
{
    extern __shared__ char sh[];
    const int tid = threadIdx.x;
    const int lane = tid & 31;
    const int wid = tid >> 5;
    const int wm = wid >> 2;          // 0..1 -> 64-row slab
    const int wn = wid & 3;           // 0..3 -> 32-col slab
    const int m0 = blockIdx.y * 128;
    const int n0 = blockIdx.x * 128;

    float acc[4][4][4];
#pragma unroll
    for (int mt = 0; mt < 4; mt++)
#pragma unroll
        for (int nt = 0; nt < 4; nt++)
#pragma unroll
            for (int q = 0; q < 4; q++) acc[mt][nt][q] = 0.f;

    const __half* gsrc[4] = {Ahi, Alo, Bhi, Blo};

    auto stage_load = [&](int s, int kt) {
        char* base = sh + s * GK_STGB;
#pragma unroll
        for (int arr = 0; arr < 4; arr++) {
            const __half* g = gsrc[arr];
            const int row0 = (arr < 2) ? m0 : n0;
#pragma unroll
            for (int i = 0; i < 2; i++) {
                int c = tid + i * 256;
                int row = c >> 2, seg = c & 3;
                uint32_t off = swz64((uint32_t)(row * 64 + seg * 16));
                uint32_t dst = smem_u32(base + arr * GK_ARB + off);
                const __half* src = g + (size_t)(row0 + row) * K_ + kt * 32 + seg * 8;
                CP_ASYNC16(dst, src);
            }
        }
    };

    const int a_row = (lane & 15);
    const int a_col = (lane >> 4) * 8;
    const int b_row = ((lane & 16) ? 8 : 0) + (lane & 7);
    const int b_col = ((lane & 8) ? 8 : 0);

    stage_load(0, 0); CP_COMMIT();
    stage_load(1, 1); CP_COMMIT();

    constexpr int KT = K_ / 32;
    for (int kt = 0; kt < KT; kt++) {
        if (kt + 1 < KT) CP_WAIT1(); else CP_WAIT0();
        __syncthreads();
        if (kt + 2 < KT) { stage_load((kt + 2) % 3, kt + 2); CP_COMMIT(); }

        const uint32_t ah_b = smem_u32(sh + (kt % 3) * GK_STGB);
        const uint32_t al_b = ah_b + GK_ARB;
        const uint32_t bh_b = ah_b + 2 * GK_ARB;
        const uint32_t bl_b = ah_b + 3 * GK_ARB;

#pragma unroll
        for (int ks = 0; ks < 2; ks++) {
            const int k0 = ks * 16;
            // B frags resident: 2 p x (hi+lo) = 16 regs
            uint32_t bh[2][4], bl[2][4];
#pragma unroll
            for (int p = 0; p < 2; p++) {
                const int nB = wn * 32 + p * 16;
                uint32_t off = swz64((uint32_t)((nB + b_row) * 64 + (k0 + b_col) * 2));
                LDSM_X4(bh[p][0], bh[p][1], bh[p][2], bh[p][3], bh_b + off);
                LDSM_X4(bl[p][0], bl[p][1], bl[p][2], bl[p][3], bl_b + off);
            }
            // A frags transient per mt: 8 regs
#pragma unroll
            for (int mt = 0; mt < 4; mt++) {
                const int rA = wm * 64 + mt * 16;
                uint32_t off = swz64((uint32_t)((rA + a_row) * 64 + (k0 + a_col) * 2));
                uint32_t ah0, ah1, ah2, ah3, al0, al1, al2, al3;
                LDSM_X4(ah0, ah1, ah2, ah3, ah_b + off);
                LDSM_X4(al0, al1, al2, al3, al_b + off);
#pragma unroll
                for (int p = 0; p < 2; p++) {
#pragma unroll
                    for (int t = 0; t < 2; t++) {
                        const int nt = p * 2 + t;
                        MMA16816(acc[mt][nt], ah0, ah1, ah2, ah3, bh[p][t * 2], bh[p][t * 2 + 1]);
                        MMA16816(acc[mt][nt], ah0, ah1, ah2, ah3, bl[p][t * 2], bl[p][t * 2 + 1]);
                        MMA16816(acc[mt][nt], al0, al1, al2, al3, bh[p][t * 2], bh[p][t * 2 + 1]);
                    }
                }
            }
        }
    }

#pragma unroll
    for (int mt = 0; mt < 4; mt++) {
#pragma unroll
        for (int nt = 0; nt < 4; nt++) {
            const int row = m0 + wm * 64 + mt * 16 + (lane >> 2);
            const int col = n0 + wn * 32 + nt * 8 + 2 * (lane & 3);
#pragma unroll
            for (int rr = 0; rr < 2; rr++) {
                float c0 = acc[mt][nt][rr * 2], c1 = acc[mt][nt][rr * 2 + 1];
                size_t idx = (size_t)(row + rr * 8) * N_ + col;
                if (OUT_SPLIT) {
                    uint32_t hi = f2h2(c0, c1);
                    uint32_t lo = f2h2_lo(c0, c1, hi);
                    *(uint32_t*)(Chi + idx) = hi;
                    *(uint32_t*)(Clo + idx) = lo;
                } else {
                    *(float2*)(C + idx) = make_float2(c0, c1);
                }
            }
        }
    }
}

// ---------------------------------------------------------------------------
// HMMA flash attention (causal). CTA: 128 q-rows x one (b,h); BKV=64.
// 4-stage cp.async K/V pipeline, 1 sync per tile. V via ldmatrix.trans.
// 8 warps x (16 rows x 64 cols). smem stride 72 halves. (Unchanged — measured
// ~184us in R8/R10.)
// ---------------------------------------------------------------------------
#define AST 72
#define KV_ARB  (64 * AST * 2)            // 9216 B per K/V array
#define KV_STGB (4 * KV_ARB)              // 36864 B per stage
#define Q_ARB   (128 * AST * 2)           // 18432 B
#define ATTN_SMEM (2 * Q_ARB + 4 * KV_STGB)  // 184320 B

__global__ __launch_bounds__(256, 1) void attn_hmma()
{
    extern __shared__ char sha[];
    __half* Qhi = (__half*)sha;
    __half* Qlo = (__half*)(sha + Q_ARB);
    char* kv0 = sha + 2 * Q_ARB;

    const int tid = threadIdx.x;
    const int lane = tid & 31;
    const int wid = tid >> 5;
    const int qt = (int)gridDim.x - 1 - (int)blockIdx.x;   // heavy CTAs first
    const int bh = blockIdx.y;
    const int b = bh >> 4;
    const int h = bh & 15;

    const __half* ghi = g_qkvhi + (size_t)b * T_ * (3 * D_) + h * HD_;
    const __half* glo = g_qkvlo + (size_t)b * T_ * (3 * D_) + h * HD_;

    auto kv_load = [&](int s, int j) {
        char* base = kv0 + s * KV_STGB;
#pragma unroll
        for (int i = 0; i < 2; i++) {
            int c = tid + i * 256;
            int row = c >> 3, seg = c & 7;
            size_t gb = (size_t)(j * 64 + row) * (3 * D_) + seg * 8;
            uint32_t doff = (uint32_t)(row * AST + seg * 8) * 2;
            CP_ASYNC16(smem_u32(base + 0 * KV_ARB + doff), ghi + gb + D_);
            CP_ASYNC16(smem_u32(base + 1 * KV_ARB + doff), glo + gb + D_);
            CP_ASYNC16(smem_u32(base + 2 * KV_ARB + doff), ghi + gb + 2 * D_);
            CP_ASYNC16(smem_u32(base + 3 * KV_ARB + doff), glo + gb + 2 * D_);
        }
    };

    // Load Q (plain; covered by first barrier)
#pragma unroll
    for (int i = 0; i < 4; i++) {
        int c = tid + i * 256;
        int r = c >> 3, d8 = (c & 7) * 8;
        size_t g = (size_t)(qt * 128 + r) * (3 * D_) + d8;
        *(uint4*)&Qhi[r * AST + d8] = *(const uint4*)(ghi + g);
        *(uint4*)&Qlo[r * AST + d8] = *(const uint4*)(glo + g);
    }

    kv_load(0, 0); CP_COMMIT();
    kv_load(1, 1); CP_COMMIT();

    float o[8][4];
    float m[2] = {-1e30f, -1e30f}, l[2] = {0.f, 0.f};
#pragma unroll
    for (int nt = 0; nt < 8; nt++)
#pragma unroll
        for (int q = 0; q < 4; q++) o[nt][q] = 0.f;

    const int a_row = (lane & 15);
    const int a_col = (lane >> 4) * 8;
    const int b_row = ((lane & 16) ? 8 : 0) + (lane & 7);
    const int b_col = ((lane & 8) ? 8 : 0);
    const int t_row = (lane & 15);
    const int t_col = ((lane >> 4) & 1) * 8;

    const uint32_t qhi_b = smem_u32(Qhi), qlo_b = smem_u32(Qlo);

    const int JT = 2 * qt + 2;
    for (int j0 = 0; j0 < JT; j0++) {
        if (j0 + 2 < JT) { kv_load((j0 + 2) & 3, j0 + 2); CP_COMMIT(); CP_WAIT2(); }
        else if (j0 + 1 < JT) CP_WAIT1();
        else CP_WAIT0();
        __syncthreads();

        const uint32_t khi_b = smem_u32(kv0 + (j0 & 3) * KV_STGB);
        const uint32_t klo_b = khi_b + KV_ARB;
        const uint32_t vhi_b = khi_b + 2 * KV_ARB;
        const uint32_t vlo_b = khi_b + 3 * KV_ARB;

        // ---- S = Q K^T (3-pass) ----
        float sacc[8][4];
#pragma unroll
        for (int nt = 0; nt < 8; nt++)
#pragma unroll
            for (int q = 0; q < 4; q++) sacc[nt][q] = 0.f;

#pragma unroll
        for (int ks = 0; ks < 4; ks++) {
            uint32_t offA = (uint32_t)((wid * 16 + a_row) * AST + ks * 16 + a_col) * 2;
            uint32_t ah0, ah1, ah2, ah3, al0, al1, al2, al3;
            LDSM_X4(ah0, ah1, ah2, ah3, qhi_b + offA);
            LDSM_X4(al0, al1, al2, al3, qlo_b + offA);
            uint32_t bhf[4][4], blf[4][4];
#pragma unroll
            for (int p = 0; p < 4; p++) {
                uint32_t offB = (uint32_t)((p * 16 + b_row) * AST + ks * 16 + b_col) * 2;
                LDSM_X4(bhf[p][0], bhf[p][1], bhf[p][2], bhf[p][3], khi_b + offB);
                LDSM_X4(blf[p][0], blf[p][1], blf[p][2], blf[p][3], klo_b + offB);
            }
#pragma unroll
            for (int p = 0; p < 4; p++)
#pragma unroll
                for (int t = 0; t < 2; t++) {
                    const int nt = p * 2 + t;
                    MMA16816(sacc[nt], ah0, ah1, ah2, ah3, bhf[p][t * 2], bhf[p][t * 2 + 1]);
                    MMA16816(sacc[nt], ah0, ah1, ah2, ah3, blf[p][t * 2], blf[p][t * 2 + 1]);
                    MMA16816(sacc[nt], al0, al1, al2, al3, bhf[p][t * 2], bhf[p][t * 2 + 1]);
                }
        }

        // ---- softmax ----
        const bool need_mask = (j0 >= 2 * qt);
#pragma unroll
        for (int hf = 0; hf < 2; hf++) {
            const int qrow = qt * 128 + wid * 16 + (lane >> 2) + hf * 8;
            float mx = -1e30f;
#pragma unroll
            for (int nt = 0; nt < 8; nt++)
#pragma unroll
                for (int u = 0; u < 2; u++) {
                    float v = sacc[nt][hf * 2 + u] * 0.125f;
                    if (need_mask && (j0 * 64 + nt * 8 + 2 * (lane & 3) + u > qrow)) v = -1e30f;
                    sacc[nt][hf * 2 + u] = v;
                    mx = fmaxf(mx, v);
                }
            mx = fmaxf(mx, __shfl_xor_sync(0xffffffffu, mx, 1));
            mx = fmaxf(mx, __shfl_xor_sync(0xffffffffu, mx, 2));
            float mnew = fmaxf(m[hf], mx);
            float corr = __expf(m[hf] - mnew);
            m[hf] = mnew;
            float ls = 0.f;
#pragma unroll
            for (int nt = 0; nt < 8; nt++)
#pragma unroll
                for (int u = 0; u < 2; u++) {
                    float p = __expf(sacc[nt][hf * 2 + u] - mnew);
                    sacc[nt][hf * 2 + u] = p;
                    ls += p;
                }
            ls += __shfl_xor_sync(0xffffffffu, ls, 1);
            ls += __shfl_xor_sync(0xffffffffu, ls, 2);
            l[hf] = l[hf] * corr + ls;
#pragma unroll
            for (int nt = 0; nt < 8; nt++)
#pragma unroll
                for (int u = 0; u < 2; u++) o[nt][hf * 2 + u] *= corr;
        }

        // ---- O += P V ----
#pragma unroll
        for (int ks = 0; ks < 4; ks++) {
            uint32_t a0h = f2h2(sacc[2 * ks][0], sacc[2 * ks][1]);
            uint32_t a1h = f2h2(sacc[2 * ks][2], sacc[2 * ks][3]);
            uint32_t a2h = f2h2(sacc[2 * ks + 1][0], sacc[2 * ks + 1][1]);
            uint32_t a3h = f2h2(sacc[2 * ks + 1][2], sacc[2 * ks + 1][3]);
            uint32_t a0l = f2h2_lo(sacc[2 * ks][0], sacc[2 * ks][1], a0h);
            uint32_t a1l = f2h2_lo(sacc[2 * ks][2], sacc[2 * ks][3], a1h);
            uint32_t a2l = f2h2_lo(sacc[2 * ks + 1][0], sacc[2 * ks + 1][1], a2h);
            uint32_t a3l = f2h2_lo(sacc[2 * ks + 1][2], sacc[2 * ks + 1][3], a3h);
#pragma unroll
            for (int p = 0; p < 4; p++) {
                uint32_t offV = (uint32_t)((ks * 16 + t_row) * AST + p * 16 + t_col) * 2;
                uint32_t bh0, bh1, bh2, bh3, bl0, bl1, bl2, bl3;
                LDSM_X4_T(bh0, bh1, bh2, bh3, vhi_b + offV);
                LDSM_X4_T(bl0, bl1, bl2, bl3, vlo_b + offV);
                MMA16816(o[p * 2 + 0], a0h, a1h, a2h, a3h, bh0, bh1);
                MMA16816(o[p * 2 + 0], a0h, a1h, a2h, a3h, bl0, bl1);
                MMA16816(o[p * 2 + 0], a0l, a1l, a2l, a3l, bh0, bh1);
                MMA16816(o[p * 2 + 1], a0h, a1h, a2h, a3h, bh2, bh3);
                MMA16816(o[p * 2 + 1], a0h, a1h, a2h, a3h, bl2, bl3);
                MMA16816(o[p * 2 + 1], a0l, a1l, a2l, a3l, bh2, bh3);
            }
        }
    }

    // Epilogue: y -> hi/lo halves
    float inv0 = 1.f / l[0], inv1 = 1.f / l[1];
#pragma unroll
    for (int nt = 0; nt < 8; nt++) {
        const int row = qt * 128 + wid * 16 + (lane >> 2);
        const int col = h * HD_ + nt * 8 + 2 * (lane & 3);
#pragma unroll
        for (int rr = 0; rr < 2; rr++) {
            float inv = rr ? inv1 : inv0;
            float v0 = o[nt][rr * 2] * inv, v1 = o[nt][rr * 2 + 1] * inv;
            size_t idx = ((size_t)b * T_ + row + rr * 8) * D_ + col;
            uint32_t hi = f2h2(v0, v1);
            uint32_t lo = f2h2_lo(v0, v1, hi);
            *(uint32_t*)(g_yhi + idx) = hi;
            *(uint32_t*)(g_ylo + idx) = lo;
        }
    }
}

// ---------------------------------------------------------------------------
extern "C" void kernel_launch(void* const* d_in, const int* in_sizes, int n_in,
                              void* d_out, int out_size)
{
    const float* x      = (const float*)d_in[0];
    const float* w_qkv  = (const float*)d_in[1];
    const float* w_proj = (const float*)d_in[2];
    float* out = (float*)d_out;

    static bool attr_set = false;
    if (!attr_set) {
        cudaFuncSetAttribute(attn_hmma, cudaFuncAttributeMaxDynamicSharedMemorySize,
                             ATTN_SMEM);
        cudaFuncSetAttribute(hmma_gemm<3 * D_, D_, 1>,
                             cudaFuncAttributeMaxDynamicSharedMemorySize, GK_SMEM);
        cudaFuncSetAttribute(hmma_gemm<D_, D_, 0>,
                             cudaFuncAttributeMaxDynamicSharedMemorySize, GK_SMEM);
        attr_set = true;
    }

    __half *xhi, *xlo, *wqh, *wql, *wph, *wpl, *yhi, *ylo, *qkvh, *qkvl;
    cudaGetSymbolAddress((void**)&xhi, g_xhi);
    cudaGetSymbolAddress((void**)&xlo, g_xlo);
    cudaGetSymbolAddress((void**)&wqh, g_wqkvhi);
    cudaGetSymbolAddress((void**)&wql, g_wqkvlo);
    cudaGetSymbolAddress((void**)&wph, g_wphi);
    cudaGetSymbolAddress((void**)&wpl, g_wplo);
    cudaGetSymbolAddress((void**)&yhi, g_yhi);
    cudaGetSymbolAddress((void**)&ylo, g_ylo);
    cudaGetSymbolAddress((void**)&qkvh, g_qkvhi);
    cudaGetSymbolAddress((void**)&qkvl, g_qkvlo);

    // Split inputs
    {
        int n4 = M_ROWS * D_ / 4;
        split_kernel<<<(n4 + 255) / 256, 256>>>(x, xhi, xlo, n4);
        n4 = 3 * D_ * D_ / 4;
        split_kernel<<<(n4 + 255) / 256, 256>>>(w_qkv, wqh, wql, n4);
        n4 = D_ * D_ / 4;
        split_kernel<<<(n4 + 255) / 256, 256>>>(w_proj, wph, wpl, n4);
    }

    // QKV GEMM -> hi/lo halves
    {
        dim3 grid(3 * D_ / 128, M_ROWS / 128);
        hmma_gemm<3 * D_, D_, 1><<<grid, 256, GK_SMEM>>>(xhi, xlo, wqh, wql,
                                                         nullptr, qkvh, qkvl);
    }

    // HMMA attention -> y hi/lo
    {
        dim3 grid(T_ / 128, B_ * H_);
        attn_hmma<<<grid, 256, ATTN_SMEM>>>();
    }

    // Proj GEMM -> fp32 out
    {
        dim3 grid(D_ / 128, M_ROWS / 128);
        hmma_gemm<D_, D_, 0><<<grid, 256, GK_SMEM>>>(yhi, ylo, wph, wpl,
                                                     out, nullptr, nullptr);
    }
}

// round 15
// speedup vs baseline: 1.0632x; 1.0632x over previous
#include <cuda_runtime.h>
#include <cuda_fp16.h>
#include <cstdint>

// Problem constants
#define B_  2
#define T_  2048
#define D_  1024
#define H_  16
#define HD_ 64
#define M_ROWS (B_ * T_)   // 4096

// ---------------------------------------------------------------------------
// Scratch (allocation-free rule: __device__ globals)
// ---------------------------------------------------------------------------
__device__ __half g_xhi[(size_t)M_ROWS * D_];
__device__ __half g_xlo[(size_t)M_ROWS * D_];
__device__ __half g_wqkvhi[(size_t)3 * D_ * D_];
__device__ __half g_wqkvlo[(size_t)3 * D_ * D_];
__device__ __half g_wphi[(size_t)D_ * D_];
__device__ __half g_wplo[(size_t)D_ * D_];
__device__ __half g_qkvhi[(size_t)M_ROWS * 3 * D_];
__device__ __half g_qkvlo[(size_t)M_ROWS * 3 * D_];
__device__ __half g_yhi[(size_t)M_ROWS * D_];
__device__ __half g_ylo[(size_t)M_ROWS * D_];

// ---------------------------------------------------------------------------
// Helpers (baseline PTX only)
// ---------------------------------------------------------------------------
__device__ __forceinline__ uint32_t smem_u32(const void* p) {
    uint32_t a;
    asm("{ .reg .u64 t; cvta.to.shared.u64 t, %1; cvt.u32.u64 %0, t; }" : "=r"(a) : "l"(p));
    return a;
}
__device__ __forceinline__ float ex2f(float x) {
    float y;
    asm("ex2.approx.f32 %0, %1;" : "=f"(y) : "f"(x));
    return y;
}

#define CP_ASYNC16(dst, src) \
    asm volatile("cp.async.cg.shared.global [%0], [%1], 16;" :: "r"(dst), "l"(src) : "memory")
#define CP_COMMIT() asm volatile("cp.async.commit_group;" ::: "memory")
#define CP_WAIT1()  asm volatile("cp.async.wait_group 1;" ::: "memory")
#define CP_WAIT0()  asm volatile("cp.async.wait_group 0;" ::: "memory")

#define LDSM_X4(r0, r1, r2, r3, addr)                                          \
    asm volatile("ldmatrix.sync.aligned.m8n8.x4.shared.b16 {%0,%1,%2,%3}, [%4];" \
                 : "=r"(r0), "=r"(r1), "=r"(r2), "=r"(r3) : "r"(addr))

#define LDSM_X4_T(r0, r1, r2, r3, addr)                                        \
    asm volatile("ldmatrix.sync.aligned.m8n8.x4.trans.shared.b16 {%0,%1,%2,%3}, [%4];" \
                 : "=r"(r0), "=r"(r1), "=r"(r2), "=r"(r3) : "r"(addr))

#define MMA16816(c, a0, a1, a2, a3, b0, b1)                                    \
    asm volatile("mma.sync.aligned.m16n8k16.row.col.f32.f16.f16.f32 "          \
                 "{%0,%1,%2,%3}, {%4,%5,%6,%7}, {%8,%9}, {%0,%1,%2,%3};"       \
                 : "+f"((c)[0]), "+f"((c)[1]), "+f"((c)[2]), "+f"((c)[3])      \
                 : "r"(a0), "r"(a1), "r"(a2), "r"(a3), "r"(b0), "r"(b1))

__device__ __forceinline__ uint32_t f2h2(float a, float b) {
    __half2 t = __floats2half2_rn(a, b);
    return *reinterpret_cast<uint32_t*>(&t);
}
__device__ __forceinline__ uint32_t f2h2_lo(float a, float b, uint32_t hi) {
    __half2 h = *reinterpret_cast<__half2*>(&hi);
    __half2 t = __floats2half2_rn(a - __low2float(h), b - __high2float(h));
    return *reinterpret_cast<uint32_t*>(&t);
}
// 64B-row swizzle: 8 consecutive rows hit 8 distinct 16B banks per chunk.
__device__ __forceinline__ uint32_t swz64(uint32_t off) {
    return off ^ (((off >> 7) & 3) << 4);
}

// ---------------------------------------------------------------------------
// Merged split kernel: fp32 -> (hi, lo) fp16 for x, w_qkv, w_proj in one launch
// ---------------------------------------------------------------------------
#define N4_X  (M_ROWS * D_ / 4)
#define N4_WQ (3 * D_ * D_ / 4)
#define N4_WP (D_ * D_ / 4)

__global__ void split_all_kernel(const float* __restrict__ x,
                                 const float* __restrict__ wq,
                                 const float* __restrict__ wp) {
    int i = blockIdx.x * blockDim.x + threadIdx.x;
    const float* src;
    __half *hi, *lo;
    int j = i;
    if (j < N4_X) {
        src = x; hi = g_xhi; lo = g_xlo;
    } else if ((j -= N4_X) < N4_WQ) {
        src = wq; hi = g_wqkvhi; lo = g_wqkvlo;
    } else if ((j -= N4_WQ) < N4_WP) {
        src = wp; hi = g_wphi; lo = g_wplo;
    } else return;
    float4 v = ((const float4*)src)[j];
    float f[4] = {v.x, v.y, v.z, v.w};
    __half h[4], l[4];
#pragma unroll
    for (int k = 0; k < 4; k++) {
        h[k] = __float2half_rn(f[k]);
        l[k] = __float2half_rn(f[k] - __half2float(h[k]));
    }
    ((__half2*)hi)[j * 2 + 0] = __halves2half2(h[0], h[1]);
    ((__half2*)hi)[j * 2 + 1] = __halves2half2(h[2], h[3]);
    ((__half2*)lo)[j * 2 + 0] = __halves2half2(l[0], l[1]);
    ((__half2*)lo)[j * 2 + 1] = __halves2half2(l[2], l[3]);
}

// ---------------------------------------------------------------------------
// HMMA fp16-split GEMM — EXACT R10 config (measured best: 197.5us QKV).
// CTA 128x128, 4 warps (2M x 2N), warp 64x64, 128 threads, 2 CTAs/SM.
// 3-stage cp.async pipeline, 1 sync/iter, B-frags resident, A transient.
// ---------------------------------------------------------------------------
#define GK_ARB  8192
#define GK_STGB 32768
#define GK_SMEM (3 * GK_STGB)

template <int N_, int K_, int OUT_SPLIT>
__global__ __launch_bounds__(128, 2) void hmma_gemm(
    const __half* __restrict__ Ahi, const __half* __restrict__ Alo,
    const __half* __restrict__ Bhi, const __half* __restrict__ Blo,
    float* __restrict__ C, __half* __restrict__ Chi, __half* __restrict__ Clo)
{
    extern __shared__ char sh[];
    const int tid = threadIdx.x;
    const int lane = tid & 31;
    const int wid = tid >> 5;
    const int wm = wid >> 1;
    const int wn = wid & 1;
    const int m0 = blockIdx.y * 128;
    const int n0 = blockIdx.x * 128;

    float acc[4][8][4];
#pragma unroll
    for (int mt = 0; mt < 4; mt++)
#pragma unroll
        for (int nt = 0; nt < 8; nt++)
#pragma unroll
            for (int q = 0; q < 4; q++) acc[mt][nt][q] = 0.f;

    const __half* gsrc[4] = {Ahi, Alo, Bhi, Blo};

    auto stage_load = [&](int s, int kt) {
        char* base = sh + s * GK_STGB;
#pragma unroll
        for (int arr = 0; arr < 4; arr++) {
            const __half* g = gsrc[arr];
            const int row0 = (arr < 2) ? m0 : n0;
#pragma unroll
            for (int i = 0; i < 4; i++) {
                int c = tid + i * 128;
                int row = c >> 2, seg = c & 3;
                uint32_t off = swz64((uint32_t)(row * 64 + seg * 16));
                uint32_t dst = smem_u32(base + arr * GK_ARB + off);
                const __half* src = g + (size_t)(row0 + row) * K_ + kt * 32 + seg * 8;
                CP_ASYNC16(dst, src);
            }
        }
    };

    const int a_row = (lane & 15);
    const int a_col = (lane >> 4) * 8;
    const int b_row = ((lane & 16) ? 8 : 0) + (lane & 7);
    const int b_col = ((lane & 8) ? 8 : 0);

    stage_load(0, 0); CP_COMMIT();
    stage_load(1, 1); CP_COMMIT();

    constexpr int KT = K_ / 32;
    for (int kt = 0; kt < KT; kt++) {
        if (kt + 1 < KT) CP_WAIT1(); else CP_WAIT0();
        __syncthreads();
        if (kt + 2 < KT) { stage_load((kt + 2) % 3, kt + 2); CP_COMMIT(); }

        const uint32_t ah_b = smem_u32(sh + (kt % 3) * GK_STGB);
        const uint32_t al_b = ah_b + GK_ARB;
        const uint32_t bh_b = ah_b + 2 * GK_ARB;
        const uint32_t bl_b = ah_b + 3 * GK_ARB;

#pragma unroll
        for (int ks = 0; ks < 2; ks++) {
            const int k0 = ks * 16;
            uint32_t bh[4][4], bl[4][4];
#pragma unroll
            for (int p = 0; p < 4; p++) {
                const int nB = wn * 64 + p * 16;
                uint32_t off = swz64((uint32_t)((nB + b_row) * 64 + (k0 + b_col) * 2));
                LDSM_X4(bh[p][0], bh[p][1], bh[p][2], bh[p][3], bh_b + off);
                LDSM_X4(bl[p][0], bl[p][1], bl[p][2], bl[p][3], bl_b + off);
            }
#pragma unroll
            for (int mt = 0; mt < 4; mt++) {
                const int rA = wm * 64 + mt * 16;
                uint32_t off = swz64((uint32_t)((rA + a_row) * 64 + (k0 + a_col) * 2));
                uint32_t ah0, ah1, ah2, ah3, al0, al1, al2, al3;
                LDSM_X4(ah0, ah1, ah2, ah3, ah_b + off);
                LDSM_X4(al0, al1, al2, al3, al_b + off);
#pragma unroll
                for (int p = 0; p < 4; p++) {
#pragma unroll
                    for (int t = 0; t < 2; t++) {
                        const int nt = p * 2 + t;
                        MMA16816(acc[mt][nt], ah0, ah1, ah2, ah3, bh[p][t * 2], bh[p][t * 2 + 1]);
                        MMA16816(acc[mt][nt], ah0, ah1, ah2, ah3, bl[p][t * 2], bl[p][t * 2 + 1]);
                        MMA16816(acc[mt][nt], al0, al1, al2, al3, bh[p][t * 2], bh[p][t * 2 + 1]);
                    }
                }
            }
        }
    }

#pragma unroll
    for (int mt = 0; mt < 4; mt++) {
#pragma unroll
        for (int nt = 0; nt < 8; nt++) {
            const int row = m0 + wm * 64 + mt * 16 + (lane >> 2);
            const int col = n0 + wn * 64 + nt * 8 + 2 * (lane & 3);
#pragma unroll
            for (int rr = 0; rr < 2; rr++) {
                float c0 = acc[mt][nt][rr * 2], c1 = acc[mt][nt][rr * 2 + 1];
                size_t idx = (size_t)(row + rr * 8) * N_ + col;
                if (OUT_SPLIT) {
                    uint32_t hi = f2h2(c0, c1);
                    uint32_t lo = f2h2_lo(c0, c1, hi);
                    *(uint32_t*)(Chi + idx) = hi;
                    *(uint32_t*)(Clo + idx) = lo;
                } else {
                    *(float2*)(C + idx) = make_float2(c0, c1);
                }
            }
        }
    }
}

// ---------------------------------------------------------------------------
// HMMA flash attention (causal). CTA: 128 q-rows x one (b,h).
// 128-col pipeline stages (2 x 73.7KB): ONE barrier per two 64-col kv tiles
// -> double the inter-warp skew window (overlaps softmax MUFU with MMA).
// ex2.approx with pre-folded log2e. V via ldmatrix.trans.
// ---------------------------------------------------------------------------
#define AST 72
#define TILE_B  (64 * AST * 2)            // 9216 B: one 64-row array tile
#define ARR2_B  (2 * TILE_B)              // 18432 B: 128-row array
#define STG2_B  (4 * ARR2_B)              // 73728 B per stage
#define Q_ARB   (128 * AST * 2)           // 18432 B
#define ATTN_SMEM (2 * Q_ARB + 2 * STG2_B)  // 184320 B
#define SC2 0.18033688011112042f          // 0.125 * log2(e)

__global__ __launch_bounds__(256, 1) void attn_hmma()
{
    extern __shared__ char sha[];
    __half* Qhi = (__half*)sha;
    __half* Qlo = (__half*)(sha + Q_ARB);
    char* kv0 = sha + 2 * Q_ARB;

    const int tid = threadIdx.x;
    const int lane = tid & 31;
    const int wid = tid >> 5;
    const int qt = (int)gridDim.x - 1 - (int)blockIdx.x;   // heavy CTAs first
    const int bh = blockIdx.y;
    const int b = bh >> 4;
    const int h = bh & 15;

    const __half* ghi = g_qkvhi + (size_t)b * T_ * (3 * D_) + h * HD_;
    const __half* glo = g_qkvlo + (size_t)b * T_ * (3 * D_) + h * HD_;

    // Load one 128-row stage (two 64-col kv tiles): K + V, hi + lo
    auto kv_load = [&](int s, int js) {
        char* base = kv0 + s * STG2_B;
#pragma unroll
        for (int i = 0; i < 4; i++) {
            int c = tid + i * 256;
            int row = c >> 3, seg = c & 7;
            size_t gb = (size_t)(js * 128 + row) * (3 * D_) + seg * 8;
            uint32_t doff = (uint32_t)(row * AST + seg * 8) * 2;
            CP_ASYNC16(smem_u32(base + 0 * ARR2_B + doff), ghi + gb + D_);
            CP_ASYNC16(smem_u32(base + 1 * ARR2_B + doff), glo + gb + D_);
            CP_ASYNC16(smem_u32(base + 2 * ARR2_B + doff), ghi + gb + 2 * D_);
            CP_ASYNC16(smem_u32(base + 3 * ARR2_B + doff), glo + gb + 2 * D_);
        }
    };

    // Load Q (plain; first barrier covers visibility)
#pragma unroll
    for (int i = 0; i < 4; i++) {
        int c = tid + i * 256;
        int r = c >> 3, d8 = (c & 7) * 8;
        size_t g = (size_t)(qt * 128 + r) * (3 * D_) + d8;
        *(uint4*)&Qhi[r * AST + d8] = *(const uint4*)(ghi + g);
        *(uint4*)&Qlo[r * AST + d8] = *(const uint4*)(glo + g);
    }

    kv_load(0, 0); CP_COMMIT();

    float o[8][4];
    float m[2] = {-1e30f, -1e30f}, l[2] = {0.f, 0.f};
#pragma unroll
    for (int nt = 0; nt < 8; nt++)
#pragma unroll
        for (int q = 0; q < 4; q++) o[nt][q] = 0.f;

    const int a_row = (lane & 15);
    const int a_col = (lane >> 4) * 8;
    const int b_row = ((lane & 16) ? 8 : 0) + (lane & 7);
    const int b_col = ((lane & 8) ? 8 : 0);
    const int t_row = (lane & 15);
    const int t_col = ((lane >> 4) & 1) * 8;

    const uint32_t qhi_b = smem_u32(Qhi), qlo_b = smem_u32(Qlo);

    const int JS = qt + 1;                 // 128-col stages
    for (int js = 0; js < JS; js++) {
        CP_WAIT0();
        __syncthreads();
        // Prefetch next stage AFTER barrier (buffer (js+1)&1 != js&1; stage
        // js-1 readers are past the barrier -> no WAR hazard at depth 2).
        if (js + 1 < JS) { kv_load((js + 1) & 1, js + 1); CP_COMMIT(); }

        const char* sb = kv0 + (js & 1) * STG2_B;

#pragma unroll 1
        for (int sub = 0; sub < 2; sub++) {
            const int j0 = 2 * js + sub;
            const uint32_t khi_b = smem_u32(sb + sub * TILE_B);
            const uint32_t klo_b = khi_b + ARR2_B;
            const uint32_t vhi_b = khi_b + 2 * ARR2_B;
            const uint32_t vlo_b = khi_b + 3 * ARR2_B;

            // ---- S = Q K^T (3-pass) ----
            float sacc[8][4];
#pragma unroll
            for (int nt = 0; nt < 8; nt++)
#pragma unroll
                for (int q = 0; q < 4; q++) sacc[nt][q] = 0.f;

#pragma unroll
            for (int ks = 0; ks < 4; ks++) {
                uint32_t offA = (uint32_t)((wid * 16 + a_row) * AST + ks * 16 + a_col) * 2;
                uint32_t ah0, ah1, ah2, ah3, al0, al1, al2, al3;
                LDSM_X4(ah0, ah1, ah2, ah3, qhi_b + offA);
                LDSM_X4(al0, al1, al2, al3, qlo_b + offA);
                uint32_t bhf[4][4], blf[4][4];
#pragma unroll
                for (int p = 0; p < 4; p++) {
                    uint32_t offB = (uint32_t)((p * 16 + b_row) * AST + ks * 16 + b_col) * 2;
                    LDSM_X4(bhf[p][0], bhf[p][1], bhf[p][2], bhf[p][3], khi_b + offB);
                    LDSM_X4(blf[p][0], blf[p][1], blf[p][2], blf[p][3], klo_b + offB);
                }
#pragma unroll
                for (int p = 0; p < 4; p++)
#pragma unroll
                    for (int t = 0; t < 2; t++) {
                        const int nt = p * 2 + t;
                        MMA16816(sacc[nt], ah0, ah1, ah2, ah3, bhf[p][t * 2], bhf[p][t * 2 + 1]);
                        MMA16816(sacc[nt], ah0, ah1, ah2, ah3, blf[p][t * 2], blf[p][t * 2 + 1]);
                        MMA16816(sacc[nt], al0, al1, al2, al3, bhf[p][t * 2], bhf[p][t * 2 + 1]);
                    }
            }

            // ---- softmax in exp2 domain (log2e folded into scale) ----
            const bool need_mask = (j0 >= 2 * qt);
#pragma unroll
            for (int hf = 0; hf < 2; hf++) {
                const int qrow = qt * 128 + wid * 16 + (lane >> 2) + hf * 8;
                float mx = -1e30f;
#pragma unroll
                for (int nt = 0; nt < 8; nt++)
#pragma unroll
                    for (int u = 0; u < 2; u++) {
                        float v = sacc[nt][hf * 2 + u] * SC2;
                        if (need_mask && (j0 * 64 + nt * 8 + 2 * (lane & 3) + u > qrow)) v = -1e30f;
                        sacc[nt][hf * 2 + u] = v;
                        mx = fmaxf(mx, v);
                    }
                mx = fmaxf(mx, __shfl_xor_sync(0xffffffffu, mx, 1));
                mx = fmaxf(mx, __shfl_xor_sync(0xffffffffu, mx, 2));
                float mnew = fmaxf(m[hf], mx);
                float corr = ex2f(m[hf] - mnew);
                m[hf] = mnew;
                float ls = 0.f;
#pragma unroll
                for (int nt = 0; nt < 8; nt++)
#pragma unroll
                    for (int u = 0; u < 2; u++) {
                        float p = ex2f(sacc[nt][hf * 2 + u] - mnew);
                        sacc[nt][hf * 2 + u] = p;
                        ls += p;
                    }
                ls += __shfl_xor_sync(0xffffffffu, ls, 1);
                ls += __shfl_xor_sync(0xffffffffu, ls, 2);
                l[hf] = l[hf] * corr + ls;
#pragma unroll
                for (int nt = 0; nt < 8; nt++)
#pragma unroll
                    for (int u = 0; u < 2; u++) o[nt][hf * 2 + u] *= corr;
            }

            // ---- O += P V (P frags in registers; V via ldmatrix.trans) ----
#pragma unroll
            for (int ks = 0; ks < 4; ks++) {
                uint32_t a0h = f2h2(sacc[2 * ks][0], sacc[2 * ks][1]);
                uint32_t a1h = f2h2(sacc[2 * ks][2], sacc[2 * ks][3]);
                uint32_t a2h = f2h2(sacc[2 * ks + 1][0], sacc[2 * ks + 1][1]);
                uint32_t a3h = f2h2(sacc[2 * ks + 1][2], sacc[2 * ks + 1][3]);
                uint32_t a0l = f2h2_lo(sacc[2 * ks][0], sacc[2 * ks][1], a0h);
                uint32_t a1l = f2h2_lo(sacc[2 * ks][2], sacc[2 * ks][3], a1h);
                uint32_t a2l = f2h2_lo(sacc[2 * ks + 1][0], sacc[2 * ks + 1][1], a2h);
                uint32_t a3l = f2h2_lo(sacc[2 * ks + 1][2], sacc[2 * ks + 1][3], a3h);
#pragma unroll
                for (int p = 0; p < 4; p++) {
                    uint32_t offV = (uint32_t)((ks * 16 + t_row) * AST + p * 16 + t_col) * 2;
                    uint32_t bh0, bh1, bh2, bh3, bl0, bl1, bl2, bl3;
                    LDSM_X4_T(bh0, bh1, bh2, bh3, vhi_b + offV);
                    LDSM_X4_T(bl0, bl1, bl2, bl3, vlo_b + offV);
                    MMA16816(o[p * 2 + 0], a0h, a1h, a2h, a3h, bh0, bh1);
                    MMA16816(o[p * 2 + 0], a0h, a1h, a2h, a3h, bl0, bl1);
                    MMA16816(o[p * 2 + 0], a0l, a1l, a2l, a3l, bh0, bh1);
                    MMA16816(o[p * 2 + 1], a0h, a1h, a2h, a3h, bh2, bh3);
                    MMA16816(o[p * 2 + 1], a0h, a1h, a2h, a3h, bl2, bl3);
                    MMA16816(o[p * 2 + 1], a0l, a1l, a2l, a3l, bh2, bh3);
                }
            }
        }
    }

    // Epilogue: y -> hi/lo halves
    float inv0 = 1.f / l[0], inv1 = 1.f / l[1];
#pragma unroll
    for (int nt = 0; nt < 8; nt++) {
        const int row = qt * 128 + wid * 16 + (lane >> 2);
        const int col = h * HD_ + nt * 8 + 2 * (lane & 3);
#pragma unroll
        for (int rr = 0; rr < 2; rr++) {
            float inv = rr ? inv1 : inv0;
            float v0 = o[nt][rr * 2] * inv, v1 = o[nt][rr * 2 + 1] * inv;
            size_t idx = ((size_t)b * T_ + row + rr * 8) * D_ + col;
            uint32_t hi = f2h2(v0, v1);
            uint32_t lo = f2h2_lo(v0, v1, hi);
            *(uint32_t*)(g_yhi + idx) = hi;
            *(uint32_t*)(g_ylo + idx) = lo;
        }
    }
}

// ---------------------------------------------------------------------------
extern "C" void kernel_launch(void* const* d_in, const int* in_sizes, int n_in,
                              void* d_out, int out_size)
{
    const float* x      = (const float*)d_in[0];
    const float* w_qkv  = (const float*)d_in[1];
    const float* w_proj = (const float*)d_in[2];
    float* out = (float*)d_out;

    static bool attr_set = false;
    if (!attr_set) {
        cudaFuncSetAttribute(attn_hmma, cudaFuncAttributeMaxDynamicSharedMemorySize,
                             ATTN_SMEM);
        cudaFuncSetAttribute(hmma_gemm<3 * D_, D_, 1>,
                             cudaFuncAttributeMaxDynamicSharedMemorySize, GK_SMEM);
        cudaFuncSetAttribute(hmma_gemm<D_, D_, 0>,
                             cudaFuncAttributeMaxDynamicSharedMemorySize, GK_SMEM);
        attr_set = true;
    }

    __half *xhi, *xlo, *wqh, *wql, *wph, *wpl, *yhi, *ylo, *qkvh, *qkvl;
    cudaGetSymbolAddress((void**)&xhi, g_xhi);
    cudaGetSymbolAddress((void**)&xlo, g_xlo);
    cudaGetSymbolAddress((void**)&wqh, g_wqkvhi);
    cudaGetSymbolAddress((void**)&wql, g_wqkvlo);
    cudaGetSymbolAddress((void**)&wph, g_wphi);
    cudaGetSymbolAddress((void**)&wpl, g_wplo);
    cudaGetSymbolAddress((void**)&yhi, g_yhi);
    cudaGetSymbolAddress((void**)&ylo, g_ylo);
    cudaGetSymbolAddress((void**)&qkvh, g_qkvhi);
    cudaGetSymbolAddress((void**)&qkvl, g_qkvlo);

    // Split inputs (single launch)
    {
        int total = N4_X + N4_WQ + N4_WP;
        split_all_kernel<<<(total + 255) / 256, 256>>>(x, w_qkv, w_proj);
    }

    // QKV GEMM -> hi/lo halves (R10 config)
    {
        dim3 grid(3 * D_ / 128, M_ROWS / 128);
        hmma_gemm<3 * D_, D_, 1><<<grid, 128, GK_SMEM>>>(xhi, xlo, wqh, wql,
                                                         nullptr, qkvh, qkvl);
    }

    // HMMA attention -> y hi/lo
    {
        dim3 grid(T_ / 128, B_ * H_);
        attn_hmma<<<grid, 256, ATTN_SMEM>>>();
    }

    // Proj GEMM -> fp32 out (R10 config)
    {
        dim3 grid(D_ / 128, M_ROWS / 128);
        hmma_gemm<D_, D_, 0><<<grid, 128, GK_SMEM>>>(yhi, ylo, wph, wpl,
                                                     out, nullptr, nullptr);
    }
}